// round 4
// baseline (speedup 1.0000x reference)
#include <cuda_runtime.h>
#include <stdint.h>

// Haar 2x2 DWT:
//   x: (8, 128, 512, 512) fp32, row-major
//   out: [x_hh | x_hl | x_lh | x_ll], each (8, 128, 256, 256) fp32
//
// Pure streaming kernel. Each thread handles 4 consecutive output columns
// (one float4 per output quadrant), reading 2x float4 from each of the two
// corresponding input rows. All loads/stores are 16B and warp-contiguous.

#define BC      (8 * 128)        // fused batch*channel
#define W_IN    512
#define H_IN    512
#define W_OUT   256
#define H_OUT   256
// elements per output quadrant
#define Q_ELEMS ((long long)BC * W_OUT * H_OUT)   // 67,108,864
// float4s per output quadrant
#define Q_VEC4  (Q_ELEMS / 4)                     // 16,777,216

__global__ __launch_bounds__(256)
void haar_dwt_kernel(const float* __restrict__ x, float* __restrict__ out)
{
    // one thread = one float4 of each output quadrant
    unsigned t = blockIdx.x * blockDim.x + threadIdx.x;   // < Q_VEC4 (fits u32)

    // decompose t -> (bc, h2, wq)
    unsigned wq   = t & 63u;            // 64 float4 per 256-wide output row
    unsigned rest = t >> 6;
    unsigned h2   = rest & 255u;        // output row
    unsigned bc   = rest >> 8;          // fused batch*channel

    // input row pair base: bc*512*512 + (2*h2)*512, in float4 units (/4)
    // = bc*65536 + h2*256 (float4), plus wq*2 within the row
    const float4* __restrict__ xv = reinterpret_cast<const float4*>(x);
    size_t row0 = (size_t)bc * 65536u + (size_t)h2 * 256u + (size_t)wq * 2u;
    size_t row1 = row0 + 128u;          // +512 floats = +128 float4

    float4 u0 = xv[row0];
    float4 u1 = xv[row0 + 1];
    float4 v0 = xv[row1];
    float4 v1 = xv[row1 + 1];

    // column pairs (a,b) from even row, (c,d) from odd row:
    //   pair0: (u0.x,u0.y | v0.x,v0.y)
    //   pair1: (u0.z,u0.w | v0.z,v0.w)
    //   pair2: (u1.x,u1.y | v1.x,v1.y)
    //   pair3: (u1.z,u1.w | v1.z,v1.w)
    float4 hh, hl, lh, ll;

    {
        float a = u0.x, b = u0.y, c = v0.x, d = v0.y;
        hh.x = 0.5f * (a - b - c + d);
        hl.x = 0.5f * (a + b - c - d);
        lh.x = 0.5f * (a - b + c - d);
        ll.x = 0.5f * (a + b + c + d);
    }
    {
        float a = u0.z, b = u0.w, c = v0.z, d = v0.w;
        hh.y = 0.5f * (a - b - c + d);
        hl.y = 0.5f * (a + b - c - d);
        lh.y = 0.5f * (a - b + c - d);
        ll.y = 0.5f * (a + b + c + d);
    }
    {
        float a = u1.x, b = u1.y, c = v1.x, d = v1.y;
        hh.z = 0.5f * (a - b - c + d);
        hl.z = 0.5f * (a + b - c - d);
        lh.z = 0.5f * (a - b + c - d);
        ll.z = 0.5f * (a + b + c + d);
    }
    {
        float a = u1.z, b = u1.w, c = v1.z, d = v1.w;
        hh.w = 0.5f * (a - b - c + d);
        hl.w = 0.5f * (a + b - c - d);
        lh.w = 0.5f * (a - b + c - d);
        ll.w = 0.5f * (a + b + c + d);
    }

    float4* __restrict__ ov = reinterpret_cast<float4*>(out);
    size_t o = (size_t)t;
    ov[o]              = hh;
    ov[o + Q_VEC4]     = hl;
    ov[o + 2 * Q_VEC4] = lh;
    ov[o + 3 * Q_VEC4] = ll;
}

extern "C" void kernel_launch(void* const* d_in, const int* in_sizes, int n_in,
                              void* d_out, int out_size)
{
    const float* x = (const float*)d_in[0];
    float* out = (float*)d_out;

    const unsigned threads = 256;
    const unsigned total   = (unsigned)Q_VEC4;          // 16,777,216 threads
    const unsigned blocks  = total / threads;           // 65,536

    haar_dwt_kernel<<<blocks, threads>>>(x, out);
}